// round 3
// baseline (speedup 1.0000x reference)
#include <cuda_runtime.h>
#include <stdint.h>

#define MAX_NODES 100000
#define MAX_EDGES 3200000
#define NOUT 16
#define NIN 5

// Scratch (allocation-free rule: __device__ globals).
__device__ __align__(16) float g_x[MAX_NODES * NOUT];  // linear output, 6.4 MB
__device__ float g_dis[MAX_NODES];                     // deg^-0.5
__device__ int   g_deg[MAX_NODES];                     // degree (init 1: self loop)
__device__ int   g_row[MAX_EDGES];                     // normalized src idx
__device__ int   g_col[MAX_EDGES];                     // normalized dst idx
__device__ int   g_is32;                               // edge_index dtype flag

// ---------------- kernels ----------------

__global__ void k_init_deg(int n) {
    int i = blockIdx.x * blockDim.x + threadIdx.x;
    if (i == 0) g_is32 = 0;
    if (i < n) g_deg[i] = 1;  // self loop
}

// Detect edge_index dtype. Safe region: first 6.4M int32 = 25.6MB exists in
// BOTH interpretations. If int64: odd 32-bit words are high halves of values
// in [0, 1e5) -> all zero. If int32: odd words are node ids, mostly nonzero.
__global__ void k_detect(const unsigned int* __restrict__ buf) {
    int i = blockIdx.x * blockDim.x + threadIdx.x;  // 65536 threads
    if (buf[2 * i + 1] != 0) g_is32 = 1;            // benign race
}

// Normalize indices to int32 scratch (clamped) + degree over targets.
__global__ void k_convert_deg(const void* __restrict__ eiv, int E, int n) {
    int e = blockIdx.x * blockDim.x + threadIdx.x;
    if (e >= E) return;
    int row, col;
    if (g_is32) {
        const int* p = (const int*)eiv;
        row = p[e]; col = p[E + e];
    } else {
        const long long* p = (const long long*)eiv;
        row = (int)p[e]; col = (int)p[E + e];
    }
    row = min(max(row, 0), n - 1);
    col = min(max(col, 0), n - 1);
    g_row[e] = row;
    g_col[e] = col;
    atomicAdd(&g_deg[col], 1);  // RED (result unused)
}

// x = atom @ W^T + b ; dis = deg^-1/2 ; out init = self-loop term = x/deg
__global__ void k_linear_init(const float* __restrict__ atom,
                              const float* __restrict__ W,
                              const float* __restrict__ b,
                              float* __restrict__ out, int n) {
    __shared__ float Ws[NOUT * NIN];
    __shared__ float bs[NOUT];
    if (threadIdx.x < NOUT * NIN) Ws[threadIdx.x] = W[threadIdx.x];
    if (threadIdx.x < NOUT) bs[threadIdx.x] = b[threadIdx.x];
    __syncthreads();

    int i = blockIdx.x * blockDim.x + threadIdx.x;
    if (i >= n) return;

    float a[NIN];
#pragma unroll
    for (int k = 0; k < NIN; k++) a[k] = atom[i * NIN + k];

    float deg = (float)g_deg[i];
    float invdeg = 1.0f / deg;
    g_dis[i] = rsqrtf(deg);

#pragma unroll
    for (int j = 0; j < NOUT; j++) {
        float acc = bs[j];
#pragma unroll
        for (int k = 0; k < NIN; k++) acc = fmaf(a[k], Ws[j * NIN + k], acc);
        g_x[i * NOUT + j] = acc;
        out[i * NOUT + j] = acc * invdeg;  // dis[i]*dis[i] = 1/deg
    }
}

__device__ __forceinline__ void red_add_v4(float* p, float4 v) {
    asm volatile("red.global.add.v4.f32 [%0], {%1, %2, %3, %4};"
                 :: "l"(p), "f"(v.x), "f"(v.y), "f"(v.z), "f"(v.w)
                 : "memory");
}

// scatter: 4 threads per edge, each handles 4 channels via vector RED
__global__ void k_scatter(int E, float* __restrict__ out) {
    long long t = (long long)blockIdx.x * blockDim.x + threadIdx.x;
    int e = (int)(t >> 2);
    if (e >= E) return;
    int c = ((int)t & 3) << 2;

    int row = g_row[e];
    int col = g_col[e];
    float nrm = g_dis[row] * g_dis[col];

    float4 xv = *reinterpret_cast<const float4*>(&g_x[row * NOUT + c]);
    float4 m;
    m.x = nrm * xv.x; m.y = nrm * xv.y; m.z = nrm * xv.z; m.w = nrm * xv.w;
    red_add_v4(out + (long long)col * NOUT + c, m);
}

__global__ void k_relu(float* __restrict__ out, int total) {
    int i = blockIdx.x * blockDim.x + threadIdx.x;
    if (i < total) out[i] = fmaxf(out[i], 0.0f);
}

// ---------------- launch ----------------

extern "C" void kernel_launch(void* const* d_in, const int* in_sizes, int n_in,
                              void* d_out, int out_size) {
    // Identify inputs by element count (all distinct):
    //   atom: 500000 fp32 | edge_index: 6400000 (int32 OR int64)
    //   W: 80 fp32        | b: 16 fp32
    const float* atom = nullptr;
    const void* ei = nullptr;
    const float* W = nullptr;
    const float* b = nullptr;
    int n = MAX_NODES, E = MAX_EDGES;

    for (int i = 0; i < n_in; i++) {
        int sz = in_sizes[i];
        if (sz == 16) b = (const float*)d_in[i];
        else if (sz == 80) W = (const float*)d_in[i];
        else if (sz > 1000000) { ei = d_in[i]; E = sz / 2; }
        else { atom = (const float*)d_in[i]; n = sz / NIN; }
    }
    if (E > MAX_EDGES) E = MAX_EDGES;
    if (n > MAX_NODES) n = MAX_NODES;

    float* out = (float*)d_out;
    const int B = 256;
    k_init_deg<<<(n + B - 1) / B, B>>>(n);
    k_detect<<<65536 / B, B>>>((const unsigned int*)ei);
    k_convert_deg<<<(E + B - 1) / B, B>>>(ei, E, n);
    k_linear_init<<<(n + B - 1) / B, B>>>(atom, W, b, out, n);
    {
        long long work = (long long)E * 4;
        int grid = (int)((work + B - 1) / B);
        k_scatter<<<grid, B>>>(E, out);
    }
    k_relu<<<(n * NOUT + B - 1) / B, B>>>(out, n * NOUT);
}

// round 4
// speedup vs baseline: 1.3313x; 1.3313x over previous
#include <cuda_runtime.h>
#include <stdint.h>

#define MAX_NODES 100000
#define NOUT 16
#define NIN 5

// Scratch (allocation-free rule: __device__ globals).
__device__ __align__(16) float g_x[MAX_NODES * NOUT];  // dis[i] * (W atom_i + b)
__device__ float g_dis[MAX_NODES];                     // deg^-0.5
__device__ int   g_deg[MAX_NODES];                     // degree (init 1: self loop)
__device__ int   g_is32 = 0;  // dtype flag: monotonic, converges on 1st call

// ---------------- kernels ----------------

// Fused: deg init + dtype detect.
// Detect: if int64, the odd 32-bit words of edge_index are high halves of
// values in [0,1e5) -> all zero. If int32 they are node ids, mostly nonzero.
// Flag is set-only (never reset): dtype is constant across replays.
__global__ void k_init(int n, const unsigned int* __restrict__ buf) {
    int i = blockIdx.x * blockDim.x + threadIdx.x;
    if (i < n) g_deg[i] = 1;                 // self loop
    if (i < 65536 && buf[2 * i + 1] != 0) g_is32 = 1;  // 512KB probe, safe
}

__device__ __forceinline__ int load_idx(const void* ei, long long pos, int n) {
    int v = g_is32 ? ((const int*)ei)[pos] : (int)((const long long*)ei)[pos];
    return min(max(v, 0), n - 1);
}

// degree over target (col) index — reads only the col half of edge_index
__global__ void k_deg(const void* __restrict__ ei, int E, int n) {
    int e = blockIdx.x * blockDim.x + threadIdx.x;
    if (e >= E) return;
    atomicAdd(&g_deg[load_idx(ei, (long long)E + e, n)], 1);  // RED
}

// 4 threads per node: x = atom@W^T + b; store g_x = dis*x; out init = g_x
// (out accumulates dis[row]*x[row]; final pass multiplies by dis[col]).
__global__ void k_linear(const float* __restrict__ atom,
                         const float* __restrict__ W,
                         const float* __restrict__ b,
                         float4* __restrict__ out4, int n) {
    int t = blockIdx.x * blockDim.x + threadIdx.x;
    int node = t >> 2;
    if (node >= n) return;
    int q = t & 3;          // channel quarter
    int j0 = q << 2;

    float a[NIN];
#pragma unroll
    for (int k = 0; k < NIN; k++) a[k] = __ldg(&atom[node * NIN + k]);

    float dis = rsqrtf((float)g_deg[node]);
    if (q == 0) g_dis[node] = dis;

    float r[4];
#pragma unroll
    for (int jj = 0; jj < 4; jj++) {
        int j = j0 + jj;
        float acc = __ldg(&b[j]);
#pragma unroll
        for (int k = 0; k < NIN; k++) acc = fmaf(a[k], __ldg(&W[j * NIN + k]), acc);
        r[jj] = acc * dis;
    }
    float4 v = make_float4(r[0], r[1], r[2], r[3]);
    reinterpret_cast<float4*>(g_x)[node * 4 + q] = v;
    out4[node * 4 + q] = v;  // self-loop term (pre dis[col] scaling)
}

__device__ __forceinline__ void red_add_v4(float* p, float4 v) {
    asm volatile("red.global.add.v4.f32 [%0], {%1, %2, %3, %4};"
                 :: "l"(p), "f"(v.x), "f"(v.y), "f"(v.z), "f"(v.w)
                 : "memory");
}

// scatter: 4 threads per edge; message is just g_x[row] (dis pre-folded)
__global__ void k_scatter(const void* __restrict__ ei, int E, int n,
                          float* __restrict__ out) {
    long long t = (long long)blockIdx.x * blockDim.x + threadIdx.x;
    int e = (int)(t >> 2);
    if (e >= E) return;
    int q = (int)t & 3;

    int row = load_idx(ei, e, n);
    int col = load_idx(ei, (long long)E + e, n);

    float4 xv = reinterpret_cast<const float4*>(g_x)[row * 4 + q];
    red_add_v4(out + ((long long)col << 4) + (q << 2), xv);
}

// out = relu(dis[col] * acc), vectorized
__global__ void k_finish(float4* __restrict__ out4, int n) {
    int t = blockIdx.x * blockDim.x + threadIdx.x;
    int node = t >> 2;
    if (node >= n) return;
    float dis = g_dis[node];
    float4 v = out4[t];
    v.x = fmaxf(v.x * dis, 0.0f);
    v.y = fmaxf(v.y * dis, 0.0f);
    v.z = fmaxf(v.z * dis, 0.0f);
    v.w = fmaxf(v.w * dis, 0.0f);
    out4[t] = v;
}

// ---------------- launch ----------------

extern "C" void kernel_launch(void* const* d_in, const int* in_sizes, int n_in,
                              void* d_out, int out_size) {
    // Identify inputs by element count (all distinct):
    //   atom: 500000 fp32 | edge_index: 6400000 (int32 OR int64)
    //   W: 80 fp32        | b: 16 fp32
    const float* atom = nullptr;
    const void* ei = nullptr;
    const float* W = nullptr;
    const float* b = nullptr;
    int n = MAX_NODES, E = 0;

    for (int i = 0; i < n_in; i++) {
        int sz = in_sizes[i];
        if (sz == 16) b = (const float*)d_in[i];
        else if (sz == 80) W = (const float*)d_in[i];
        else if (sz > 1000000) { ei = d_in[i]; E = sz / 2; }
        else { atom = (const float*)d_in[i]; n = sz / NIN; }
    }
    if (n > MAX_NODES) n = MAX_NODES;

    float* out = (float*)d_out;
    const int B = 256;
    int initN = (n > 65536) ? n : 65536;
    k_init<<<(initN + B - 1) / B, B>>>(n, (const unsigned int*)ei);
    k_deg<<<(E + B - 1) / B, B>>>(ei, E, n);
    k_linear<<<(n * 4 + B - 1) / B, B>>>(atom, W, b, (float4*)out, n);
    {
        long long work = (long long)E * 4;
        k_scatter<<<(int)((work + B - 1) / B), B>>>(ei, E, n, out);
    }
    k_finish<<<(n * 4 + B - 1) / B, B>>>((float4*)out, n);
}